// round 2
// baseline (speedup 1.0000x reference)
#include <cuda_runtime.h>
#include <cuda_bf16.h>
#include <math.h>

// Problem dims (fixed by reference)
#define NB 2
#define CC 8192
#define HID 4096
#define RDIM 512
#define HH 8
#define PH 64           // per-head dim
#define DD 128          // landmark chunks
#define TOPK 16
#define NROWS (NB*CC)   // 16384

// -------- device scratch (no allocations allowed) --------
__device__ float g_scale[NROWS];              // 64 KB
__device__ float g_wt[HID * RDIM];            // 8 MB, W^T with pre_norm_weight folded
__device__ float g_q[NROWS * RDIM];           // 33.5 MB, q_emb

// ============================================================
// Kernel 1: per-row inverse RMS
// ============================================================
__global__ __launch_bounds__(256) void rms_scale_kernel(const float* __restrict__ x) {
    int row = blockIdx.x;
    const float4* xr = (const float4*)(x + (size_t)row * HID);
    float sum = 0.f;
#pragma unroll
    for (int i = 0; i < 4; i++) {
        float4 v = xr[threadIdx.x + i * 256];
        sum += v.x * v.x + v.y * v.y + v.z * v.z + v.w * v.w;
    }
#pragma unroll
    for (int o = 16; o; o >>= 1) sum += __shfl_xor_sync(0xffffffffu, sum, o);
    __shared__ float red[8];
    if ((threadIdx.x & 31) == 0) red[threadIdx.x >> 5] = sum;
    __syncthreads();
    if (threadIdx.x < 8) {
        float s = red[threadIdx.x];
#pragma unroll
        for (int o = 4; o; o >>= 1) s += __shfl_xor_sync(0xffu, s, o);
        if (threadIdx.x == 0)
            g_scale[row] = rsqrtf(s * (1.0f / (float)HID) + 1e-6f);
    }
}

// ============================================================
// Kernel 2: g_wt[j][o] = W[o][j] * pre_norm_weight[j]   (tiled transpose)
// ============================================================
__global__ void prep_w_kernel(const float* __restrict__ W, const float* __restrict__ prew) {
    __shared__ float tile[32][33];
    int jb = blockIdx.x * 32;   // over HID
    int ob = blockIdx.y * 32;   // over RDIM
    int tx = threadIdx.x, ty = threadIdx.y;  // 32 x 8
#pragma unroll
    for (int r = 0; r < 4; r++) {
        int o = ob + ty + r * 8;
        tile[ty + r * 8][tx] = W[(size_t)o * HID + jb + tx];
    }
    __syncthreads();
#pragma unroll
    for (int r = 0; r < 4; r++) {
        int jl = ty + r * 8;
        int j = jb + jl;
        g_wt[(size_t)j * RDIM + ob + tx] = tile[tx][jl] * prew[j];
    }
}

// ============================================================
// Kernel 3: SGEMM  g_q[m][o] = g_scale[m] * sum_j hidden[m][j] * g_wt[j][o]
//   BM=128 BN=64 BK=16, 256 threads, thread tile 8x4
// ============================================================
#define BM 128
#define BN 64
#define BK 16
__global__ __launch_bounds__(256) void gemm_kernel(const float* __restrict__ A) {
    __shared__ __align__(16) float As[BK][BM];
    __shared__ __align__(16) float Bs[BK][BN];
    const int bm = blockIdx.y * BM;
    const int bn = blockIdx.x * BN;
    const int tid = threadIdx.x;
    const int ty = tid >> 4;   // 0..15 (m groups of 8)
    const int tx = tid & 15;   // 0..15 (n groups of 4)

    float acc[8][4];
#pragma unroll
    for (int i = 0; i < 8; i++)
#pragma unroll
        for (int j = 0; j < 4; j++) acc[i][j] = 0.f;

    for (int k0 = 0; k0 < HID; k0 += BK) {
        // load A tile (128x16) transposed into As[k][m]
#pragma unroll
        for (int i = 0; i < 2; i++) {
            int p = tid * 2 + i;      // 0..511
            int r = p >> 2;           // row 0..127
            int c4 = p & 3;           // f4 index within the 16-wide row
            float4 v = *(const float4*)(A + (size_t)(bm + r) * HID + k0 + c4 * 4);
            As[c4 * 4 + 0][r] = v.x;
            As[c4 * 4 + 1][r] = v.y;
            As[c4 * 4 + 2][r] = v.z;
            As[c4 * 4 + 3][r] = v.w;
        }
        // load B tile (16x64)
        {
            int r = tid >> 4;         // 0..15
            int c4 = tid & 15;        // 0..15
            float4 v = *(const float4*)(g_wt + (size_t)(k0 + r) * RDIM + bn + c4 * 4);
            *(float4*)&Bs[r][c4 * 4] = v;
        }
        __syncthreads();
#pragma unroll
        for (int k = 0; k < BK; k++) {
            float4 a03 = *(const float4*)&As[k][ty * 8];
            float4 a47 = *(const float4*)&As[k][ty * 8 + 4];
            float4 bv  = *(const float4*)&Bs[k][tx * 4];
            float a[8] = {a03.x, a03.y, a03.z, a03.w, a47.x, a47.y, a47.z, a47.w};
            float b[4] = {bv.x, bv.y, bv.z, bv.w};
#pragma unroll
            for (int i = 0; i < 8; i++)
#pragma unroll
                for (int j = 0; j < 4; j++) acc[i][j] += a[i] * b[j];
        }
        __syncthreads();
    }
    // epilogue: apply rms scale per row
    int mbase = bm + ty * 8;
    int nbase = bn + tx * 4;
#pragma unroll
    for (int i = 0; i < 8; i++) {
        float s = g_scale[mbase + i];
        float4 o;
        o.x = acc[i][0] * s; o.y = acc[i][1] * s; o.z = acc[i][2] * s; o.w = acc[i][3] * s;
        *(float4*)(g_q + (size_t)(mbase + i) * RDIM + nbase) = o;
    }
}

// ============================================================
// Kernel 4: scores (vs landmarks), causal top-16, index-desc sort,
//           softplus-cumsum weights. One thread per (n,c,h).
// ============================================================
__global__ __launch_bounds__(128) void scores_kernel(const float* __restrict__ lmk,
                                                     float* __restrict__ out) {
    const int n = blockIdx.z;
    const int h = blockIdx.y;
    const int c = blockIdx.x * 128 + threadIdx.x;

    // landmarks for this (n,h): [128 chunks][64] -> 32 KB smem
    __shared__ __align__(16) float4 sL[DD * 16];
    {
        int d = threadIdx.x;  // 0..127
        const float4* src = (const float4*)(lmk + ((size_t)((n * DD + d) * HH + h) << 6));
#pragma unroll
        for (int e = 0; e < 16; e++) sL[d * 16 + e] = src[e];
    }
    __syncthreads();

    // q row (64 floats) in registers
    float4 qv[16];
    const float4* qp = (const float4*)(g_q + ((size_t)(n * CC + c) * RDIM + h * PH));
#pragma unroll
    for (int e = 0; e < 16; e++) qv[e] = qp[e];

    int v = c >> 6;               // visible chunks; c<8192 -> v<=127
    float tv[TOPK];               // ascending values, tv[0] = current min
    int   ti[TOPK];
#pragma unroll
    for (int i = 0; i < TOPK; i++) { tv[i] = -INFINITY; ti[i] = -1; }

    for (int j = 0; j < v; j++) {
        float dot = 0.f;
#pragma unroll
        for (int e = 0; e < 16; e++) {
            float4 l = sL[j * 16 + e];
            dot += qv[e].x * l.x + qv[e].y * l.y + qv[e].z * l.z + qv[e].w * l.w;
        }
        float s = dot * 0.125f;   // / sqrt(64)
        if (s > tv[0]) {          // strict: ties keep earlier index (matches lax.top_k)
            bool done = false;
#pragma unroll
            for (int i = 0; i < TOPK - 1; i++) {
                if (!done) {
                    if (tv[i + 1] < s) { tv[i] = tv[i + 1]; ti[i] = ti[i + 1]; }
                    else               { tv[i] = s; ti[i] = j; done = true; }
                }
            }
            if (!done) { tv[TOPK - 1] = s; ti[TOPK - 1] = j; }
        }
    }

    // sort pairs by index descending (invalid ti=-1 sink to the end)
#pragma unroll
    for (int a = 0; a < TOPK - 1; a++)
#pragma unroll
        for (int b = 0; b < TOPK - 1 - a; b++) {
            if (ti[b] < ti[b + 1]) {
                int   t0 = ti[b]; ti[b] = ti[b + 1]; ti[b + 1] = t0;
                float t1 = tv[b]; tv[b] = tv[b + 1]; tv[b + 1] = t1;
            }
        }

    // softplus(threshold=15) cumsum -> weights
    const size_t IDX_OFF = (size_t)NB * CC * HH * TOPK;  // 2097152
    size_t base = ((size_t)(n * CC + c) * HH + h) << 4;
    float cum = 0.f;
#pragma unroll
    for (int i = 0; i < TOPK; i++) {
        bool valid = ti[i] >= 0;
        float s = valid ? tv[i] : -INFINITY;
        float sp = (s > 15.0f) ? s : log1pf(expf(s));    // s=-inf -> 0
        cum += sp;
        float w = expf(s - cum);                          // -inf -> 0
        out[base + i] = w;
        out[IDX_OFF + base + i] = valid ? (float)ti[i] : 0.0f;
    }
}

// ============================================================
extern "C" void kernel_launch(void* const* d_in, const int* in_sizes, int n_in,
                              void* d_out, int out_size) {
    const float* hidden = (const float*)d_in[0];  // (2, 8192, 4096)
    const float* lmk    = (const float*)d_in[1];  // (2, 128, 8, 64)
    const float* prew   = (const float*)d_in[2];  // (4096,)
    const float* W      = (const float*)d_in[3];  // (512, 4096)
    float* out = (float*)d_out;

    rms_scale_kernel<<<NROWS, 256>>>(hidden);
    prep_w_kernel<<<dim3(HID / 32, RDIM / 32), dim3(32, 8)>>>(W, prew);
    gemm_kernel<<<dim3(RDIM / BN, NROWS / BM), 256>>>(hidden);
    scores_kernel<<<dim3(CC / 128, HH, NB), 128>>>(lmk, out);
}